// round 3
// baseline (speedup 1.0000x reference)
#include <cuda_runtime.h>

// InteractionArch: out[b] = concat(dense[b] (128),
//        triu(k=1) of Gram([dense[b]; sparse[b].reshape(26,128)]) (351))
// B=16384, D=128, F=26, OUTW=479.
//
// One warp per sample; lane owns dims lane*4..lane*4+3 (float4) of each vector.
// Register tiling: low-14 vectors resident (phase 1+2), high vectors streamed
// (phase 2) then reloaded (phase 3). Pair partials batched in chunks of 32 and
// reduced with a 31-shuffle halving butterfly -> lane j holds chunk pair j.
// Iteration order != triu order, so a per-block smem table maps slot->out idx.

#define BNUM  16384
#define FF    26
#define NV    27
#define OUTW  479
#define NPAIR 351

__device__ __forceinline__ float dot4(const float4 a, const float4 b)
{
    float s = a.x * b.x;
    s = fmaf(a.y, b.y, s);
    s = fmaf(a.z, b.z, s);
    s = fmaf(a.w, b.w, s);
    return s;
}

// Reduce 32 lane-partial sums across the warp; lane j returns the full sum of
// element j. 31 shuffles total.
__device__ __forceinline__ float bfly32(float (&p)[32], const int lane)
{
#pragma unroll
    for (int m = 16; m >= 1; m >>= 1) {
#pragma unroll
        for (int i = 0; i < m; ++i) {
            const bool up  = (lane & m) != 0;
            float send = up ? p[i] : p[i + m];
            float recv = __shfl_xor_sync(0xffffffffu, send, m);
            float keep = up ? p[i + m] : p[i];
            p[i] = keep + recv;
        }
    }
    return p[0];
}

#define EMIT(val)                                                   \
    do {                                                            \
        p[slot] = (val);                                            \
        ++slot;                                                     \
        if (slot == 32) {                                           \
            float r = bfly32(p, lane);                              \
            int oi = tbl[chunk * 32 + lane];                        \
            ob[oi] = r;                                             \
            ++chunk;                                                \
            slot = 0;                                               \
        }                                                           \
    } while (0)

__global__ __launch_bounds__(256, 2)
void interact_kernel(const float* __restrict__ dense,
                     const float* __restrict__ sparse,
                     float* __restrict__ out)
{
    __shared__ int tbl[352];

    // ---- Build slot -> output-index table (iteration order below) ----
    for (int s = threadIdx.x; s < NPAIR; s += blockDim.x) {
        int f, g;
        if (s < 91) {                       // phase 1: f=0..12, g=f+1..13
            int f0 = 0;
            while (13 * (f0 + 1) - (f0 + 1) * f0 / 2 <= s) ++f0;
            f = f0;
            g = f + 1 + (s - (13 * f - f * (f - 1) / 2));
        } else if (s < 273) {               // phase 2: g=14..26 outer, f=0..13 inner
            int t = s - 91;
            g = 14 + t / 14;
            f = t % 14;
        } else {                            // phase 3: a=0..11, b=a+1..12 (high set)
            int t = s - 273;
            int a0 = 0;
            while (12 * (a0 + 1) - (a0 + 1) * a0 / 2 <= t) ++a0;
            int a = a0;
            int b = a + 1 + (t - (12 * a - a * (a - 1) / 2));
            f = 14 + a;
            g = 14 + b;
        }
        tbl[s] = 128 + f * 26 - f * (f - 1) / 2 + (g - f - 1);
    }
    __syncthreads();

    const int gw   = (blockIdx.x * blockDim.x + threadIdx.x) >> 5;  // sample
    const int lane = threadIdx.x & 31;

    const float4* d4 = reinterpret_cast<const float4*>(dense)  + (size_t)gw * 32;
    const float4* s4 = reinterpret_cast<const float4*>(sparse) + (size_t)gw * (FF * 32);

    float* ob = out + (size_t)gw * OUTW;

    float p[32];
    int slot = 0, chunk = 0;    // constant-folded under full unroll

    // ---- Load low 14 vectors (dense + sparse 0..12): 56 regs ----
    float4 vlo[14];
    vlo[0] = d4[lane];
#pragma unroll
    for (int i = 1; i < 14; ++i)
        vlo[i] = s4[(i - 1) * 32 + lane];

    // Dense passthrough.
    ob[lane * 4 + 0] = vlo[0].x;
    ob[lane * 4 + 1] = vlo[0].y;
    ob[lane * 4 + 2] = vlo[0].z;
    ob[lane * 4 + 3] = vlo[0].w;

    // ---- Phase 1: pairs within low set ----
#pragma unroll
    for (int f = 0; f < 13; ++f)
#pragma unroll
        for (int g = f + 1; g < 14; ++g)
            EMIT(dot4(vlo[f], vlo[g]));

    // ---- Phase 2: stream high vectors (g = 14..26), prefetch depth 1 ----
    {
        float4 u = s4[13 * 32 + lane];              // vector 14
#pragma unroll
        for (int g = 14; g < 27; ++g) {
            float4 un = u;
            if (g < 26)
                un = s4[g * 32 + lane];             // vector g+1 -> sparse row g
#pragma unroll
            for (int f = 0; f < 14; ++f)
                EMIT(dot4(vlo[f], u));
            u = un;
        }
    }

    // Keep phase-3 reloads from being hoisted (would blow register budget).
    asm volatile("" ::: "memory");

    // ---- Phase 3: reload high 13 (L2-hot), pairs within high set ----
    {
        float4 vh[13];
#pragma unroll
        for (int i = 0; i < 13; ++i)
            vh[i] = s4[(13 + i) * 32 + lane];
#pragma unroll
        for (int a = 0; a < 12; ++a)
#pragma unroll
            for (int b = a + 1; b < 13; ++b)
                EMIT(dot4(vh[a], vh[b]));
    }

    // ---- Tail: 351 = 10*32 + 31; pad slot 31 and flush ----
    p[31] = 0.0f;
    {
        float r = bfly32(p, lane);
        if (lane < 31) {
            int oi = tbl[10 * 32 + lane];
            ob[oi] = r;
        }
    }
}

extern "C" void kernel_launch(void* const* d_in, const int* in_sizes, int n_in,
                              void* d_out, int out_size)
{
    const float* dense  = (const float*)d_in[0];
    const float* sparse = (const float*)d_in[1];
    float* out = (float*)d_out;

    // 16384 samples, 1 warp each, 8 warps/block -> 2048 blocks.
    interact_kernel<<<2048, 256>>>(dense, sparse, out);
}